// round 16
// baseline (speedup 1.0000x reference)
#include <cuda_runtime.h>
#include <math.h>
#include <cstdint>

// Problem constants
#define CD   384
#define TWIN 256
#define NWIN 256
#define NTOK 65536
#define NHEADS 6
#define DHEAD 64
#define MLPD 1536
#define DHW 65536
#define HW 4096
#define QKVD 1152

// -------- scratch (device globals; allocation-free contract) --------
__device__ float g_xw [NTOK * CD];
__device__ float g_h  [NTOK * CD];
__device__ float g_qkv[(size_t)NTOK * QKVD];
__device__ float g_att[NTOK * CD];
__device__ float g_xw2[NTOK * CD];
__device__ float g_h2 [NTOK * CD];
__device__ float g_hid[(size_t)NTOK * MLPD];
__device__ float g_y  [NTOK * CD];
__device__ float g_wqkv[CD * QKVD];   // [K=384][M=1152] concat of Wq|Wk|Wv columns
__device__ float g_bqkv[QKVD];

// ---- helpers ----
__device__ __forceinline__ void mma_tf32(float* c, const uint32_t* a, const uint32_t* b) {
    asm volatile(
        "mma.sync.aligned.m16n8k8.row.col.f32.tf32.tf32.f32 "
        "{%0,%1,%2,%3}, {%4,%5,%6,%7}, {%8,%9}, {%0,%1,%2,%3};"
        : "+f"(c[0]), "+f"(c[1]), "+f"(c[2]), "+f"(c[3])
        : "r"(a[0]), "r"(a[1]), "r"(a[2]), "r"(a[3]), "r"(b[0]), "r"(b[1]));
}
__device__ __forceinline__ uint32_t smem_u32(const void* p) {
    uint32_t a;
    asm("{ .reg .u64 t; cvta.to.shared.u64 t, %1; cvt.u32.u64 %0, t; }" : "=r"(a) : "l"(p));
    return a;
}
#define CP_ASYNC16(dst, src) \
    asm volatile("cp.async.cg.shared.global [%0], [%1], 16;" :: "r"(dst), "l"(src))
#define CP_COMMIT  asm volatile("cp.async.commit_group;")
#define CP_WAIT1   asm volatile("cp.async.wait_group 1;" ::: "memory")

// ================= tensor-core tf32 GEMM (cp.async double-buffered) =================
// C[128,128] tile = A[N,K] @ B[K,M]  (B in ORIGINAL row-major [K][M] layout)
// 256 threads = 8 warps, warp tile 64x32. K-chunks of 32, 2-stage pipeline.
// 16 warps/SM (2 CTAs) to hide LDS/barrier latency that capped tensor at 53%.
// Block mapping: bcol = blockIdx.x (FAST), brow = blockIdx.y (SLOW) -> A L2-resident.
#define TG_ASTRB 144            // A row stride bytes (36 floats)
#define TG_BSTRB 544            // B row stride bytes (136 floats)
#define TG_ABYTES (128 * 144)   // 18432
#define TG_STAGEB (TG_ABYTES + 32 * 544)  // 35840
#define TG_SMEM (2 * TG_STAGEB)           // 71680

#define TG_ISSUE(cc, ss) do {                                                        \
    uint32_t aoff = sbase + (uint32_t)(ss) * TG_STAGEB;                              \
    uint32_t boff = aoff + TG_ABYTES;                                                \
    int k0 = (cc) * 32;                                                              \
    _Pragma("unroll")                                                                \
    for (int j = 0; j < 4; j++) {                                                    \
        int idx = tid + 256 * j;                                                     \
        int ar = idx >> 3, aseg = idx & 7;                                           \
        CP_ASYNC16(aoff + (uint32_t)(ar * TG_ASTRB + aseg * 16),                     \
                   A + (size_t)(brow + ar) * K + k0 + aseg * 4);                     \
        int br = idx >> 5, bseg = idx & 31;                                          \
        CP_ASYNC16(boff + (uint32_t)(br * TG_BSTRB + bseg * 16),                     \
                   B + (size_t)(k0 + br) * Mtot + bcol + bseg * 4);                  \
    } } while (0)

template<int MODE>
__global__ void __launch_bounds__(256, 2)
tgemm_kernel(const float* __restrict__ A, const float* __restrict__ B,
             const float* __restrict__ bias, const float* __restrict__ res,
             float* __restrict__ Cout, int K, int Mtot) {
    extern __shared__ float smem[];
    const uint32_t sbase = smem_u32(smem);

    const int tid  = threadIdx.x;
    const int wid  = tid >> 5;
    const int lane = tid & 31;
    const int lq   = lane >> 2, lr = lane & 3;
    const int wm   = wid & 1;       // 64-row half
    const int wn   = wid >> 1;      // 32-col quarter (0..3)
    const int brow = blockIdx.y * 128;   // SLOW index: A row tile shared by x-run
    const int bcol = blockIdx.x * 128;   // FAST index

    float acc[64];
    #pragma unroll
    for (int i = 0; i < 64; i++) acc[i] = 0.f;

    const int nk = K >> 5;

    TG_ISSUE(0, 0);
    CP_COMMIT;

    for (int c = 0; c < nk; c++) {
        const int s = c & 1;
        if (c + 1 < nk) { TG_ISSUE(c + 1, (c + 1) & 1); }
        CP_COMMIT;
        CP_WAIT1;
        __syncthreads();

        const float* sA = smem + s * (TG_STAGEB / 4);
        const float* sB = sA + (TG_ABYTES / 4);

        #pragma unroll
        for (int q = 0; q < 4; q++) {
            uint32_t af[4][4];
            #pragma unroll
            for (int am = 0; am < 4; am++) {
                const float* ap = sA + (64 * wm + 16 * am + lq) * 36 + 8 * q + lr;
                af[am][0] = __float_as_uint(ap[0]);
                af[am][1] = __float_as_uint(ap[8 * 36]);
                af[am][2] = __float_as_uint(ap[4]);
                af[am][3] = __float_as_uint(ap[8 * 36 + 4]);
            }
            uint32_t bf[4][2];
            #pragma unroll
            for (int bn = 0; bn < 4; bn++) {
                const float* bp = sB + (8 * q + lr) * 136 + 32 * wn + 8 * bn + lq;
                bf[bn][0] = __float_as_uint(bp[0]);
                bf[bn][1] = __float_as_uint(bp[4 * 136]);
            }
            #pragma unroll
            for (int am = 0; am < 4; am++)
                #pragma unroll
                for (int bn = 0; bn < 4; bn++)
                    mma_tf32(&acc[(am * 4 + bn) * 4], af[am], bf[bn]);
        }
        __syncthreads();
    }

    // epilogue
    #pragma unroll
    for (int am = 0; am < 4; am++) {
        int row0 = brow + 64 * wm + 16 * am + lq;
        #pragma unroll
        for (int bn = 0; bn < 4; bn++) {
            int col = bcol + 32 * wn + 8 * bn + 2 * lr;
            float2 bv = *(const float2*)(bias + col);
            const int ix = (am * 4 + bn) * 4;
            float2 o0 = make_float2(acc[ix + 0] + bv.x, acc[ix + 1] + bv.y);
            float2 o1 = make_float2(acc[ix + 2] + bv.x, acc[ix + 3] + bv.y);
            if (MODE == 1) {
                float2 r0 = *(const float2*)(res + (size_t)row0 * Mtot + col);
                float2 r1 = *(const float2*)(res + (size_t)(row0 + 8) * Mtot + col);
                o0.x += r0.x; o0.y += r0.y; o1.x += r1.x; o1.y += r1.y;
            }
            if (MODE == 2) {
                o0.x = 0.5f * o0.x * (1.0f + erff(o0.x * 0.7071067811865476f));
                o0.y = 0.5f * o0.y * (1.0f + erff(o0.y * 0.7071067811865476f));
                o1.x = 0.5f * o1.x * (1.0f + erff(o1.x * 0.7071067811865476f));
                o1.y = 0.5f * o1.y * (1.0f + erff(o1.y * 0.7071067811865476f));
            }
            *(float2*)(Cout + (size_t)row0 * Mtot + col) = o0;
            *(float2*)(Cout + (size_t)(row0 + 8) * Mtot + col) = o1;
        }
    }
}

// ================= QKV weight/bias concat =================
__global__ void __launch_bounds__(384) concat_qkv_kernel(const float* __restrict__ Wq,
                                                         const float* __restrict__ Wk,
                                                         const float* __restrict__ Wv) {
    int k = blockIdx.x;
    int t = threadIdx.x;
    g_wqkv[(size_t)k * QKVD + t]       = Wq[(size_t)k * CD + t];
    g_wqkv[(size_t)k * QKVD + 384 + t] = Wk[(size_t)k * CD + t];
    g_wqkv[(size_t)k * QKVD + 768 + t] = Wv[(size_t)k * CD + t];
}

__global__ void bias_concat_kernel(const float* bq, const float* bk, const float* bv) {
    int i = threadIdx.x + blockIdx.x * blockDim.x;
    if (i < 384) g_bqkv[i] = bq[i];
    else if (i < 768) g_bqkv[i] = bk[i - 384];
    else if (i < 1152) g_bqkv[i] = bv[i - 768];
}

// ================= gather (coalesced) + LN1 =================
__global__ void __launch_bounds__(384) gather_ln1_kernel(const float* __restrict__ x,
                                  const float* __restrict__ gamma,
                                  const float* __restrict__ beta) {
    __shared__ float s[384 * 9];
    __shared__ float smu[8], srs[8];

    int run = blockIdx.x;
    int p = run >> 5, td = (run >> 3) & 3, th = run & 7;
    int bd = p >> 6, bh = (p >> 3) & 7, bw = p & 7;
    int od = (bd * 4 + td + 2) & 15;
    int oh = (bh * 8 + th + 4) & 63;
    int w0 = (bw * 8 + 4) & 63;
    int w1 = (bw * 8 + 8) & 63;
    int n0 = p * 256 + td * 64 + th * 8;

    int c = threadIdx.x;
    const float* base = x + (size_t)c * DHW + od * HW + oh * 64;
    float4 fa = *(const float4*)(base + w0);
    float4 fb = *(const float4*)(base + w1);
    s[c * 9 + 0] = fa.x; s[c * 9 + 1] = fa.y; s[c * 9 + 2] = fa.z; s[c * 9 + 3] = fa.w;
    s[c * 9 + 4] = fb.x; s[c * 9 + 5] = fb.y; s[c * 9 + 6] = fb.z; s[c * 9 + 7] = fb.w;
    __syncthreads();

    int wid = c >> 5, lane = c & 31;
    if (wid < 8) {
        float sum = 0.f, sq = 0.f;
        #pragma unroll
        for (int i = 0; i < 12; i++) {
            float v = s[(lane + 32 * i) * 9 + wid];
            sum += v; sq += v * v;
        }
        #pragma unroll
        for (int o = 16; o; o >>= 1) {
            sum += __shfl_xor_sync(0xffffffffu, sum, o);
            sq  += __shfl_xor_sync(0xffffffffu, sq, o);
        }
        if (lane == 0) {
            float mu = sum * (1.f / 384.f);
            float var = sq * (1.f / 384.f) - mu * mu;
            smu[wid] = mu;
            srs[wid] = rsqrtf(var + 1e-5f);
        }
    }
    __syncthreads();

    float g = gamma[c], b = beta[c];
    #pragma unroll
    for (int j = 0; j < 8; j++) {
        float val = s[c * 9 + j];
        g_xw[(size_t)(n0 + j) * CD + c] = val;
        g_h [(size_t)(n0 + j) * CD + c] = (val - smu[j]) * srs[j] * g + b;
    }
}

// ================= LN2 =================
__global__ void ln2_kernel(const float* __restrict__ gamma,
                           const float* __restrict__ beta) {
    int n = blockIdx.x;
    int c = threadIdx.x;
    float val = g_xw2[n * CD + c];
    __shared__ float red[12];
    __shared__ float mu_s, rs_s;
    float s = val;
    #pragma unroll
    for (int o = 16; o; o >>= 1) s += __shfl_down_sync(0xffffffffu, s, o);
    if ((threadIdx.x & 31) == 0) red[threadIdx.x >> 5] = s;
    __syncthreads();
    if (threadIdx.x < 32) {
        float ts = (threadIdx.x < 12) ? red[threadIdx.x] : 0.f;
        #pragma unroll
        for (int o = 8; o; o >>= 1) ts += __shfl_down_sync(0xffffffffu, ts, o);
        if (threadIdx.x == 0) mu_s = ts * (1.f / 384.f);
    }
    __syncthreads();
    float d = val - mu_s;
    float s2 = d * d;
    #pragma unroll
    for (int o = 16; o; o >>= 1) s2 += __shfl_down_sync(0xffffffffu, s2, o);
    if ((threadIdx.x & 31) == 0) red[threadIdx.x >> 5] = s2;
    __syncthreads();
    if (threadIdx.x < 32) {
        float ts = (threadIdx.x < 12) ? red[threadIdx.x] : 0.f;
        #pragma unroll
        for (int o = 8; o; o >>= 1) ts += __shfl_down_sync(0xffffffffu, ts, o);
        if (threadIdx.x == 0) rs_s = rsqrtf(ts * (1.f / 384.f) + 1e-5f);
    }
    __syncthreads();
    g_h2[n * CD + c] = d * rs_s * gamma[c] + beta[c];
}

// ================= tensor-core flash attention (cp.async double-buffered) =================
#define AQ_STR 68
#define AK_STR 68
#define AV_STR 72
#define AP_STR 68
#define SK_OFF (256 * AQ_STR)                 // 17408 floats
#define A_STG  (64 * AK_STR + 64 * AV_STR)    // 8960 floats per KV stage
#define SP_OFF (SK_OFF + 2 * A_STG)           // 35328 floats
#define ATT_SMEM ((SP_OFF + 256 * AP_STR) * 4)  // 210944 bytes

// issue K/V block kb into stage ss (raw bits; cp.async)
#define ATT_ISSUE(kb, ss) do {                                                         \
    int r_ = tid >> 2, qt_ = tid & 3;                                                  \
    const float* krow_ = g_qkv + (size_t)(p * 256 + (kb) * 64 + r_) * QKVD + 384       \
                         + h * 64 + qt_ * 16;                                          \
    const float* vrow_ = krow_ + 384;                                                  \
    uint32_t ka_ = sb + (uint32_t)((SK_OFF + (ss) * A_STG + r_ * AK_STR + qt_ * 16) * 4); \
    uint32_t va_ = sb + (uint32_t)((SK_OFF + (ss) * A_STG + 64 * AK_STR + r_ * AV_STR + qt_ * 16) * 4); \
    _Pragma("unroll")                                                                  \
    for (int e_ = 0; e_ < 4; e_++) {                                                   \
        CP_ASYNC16(ka_ + 16 * e_, krow_ + 4 * e_);                                     \
        CP_ASYNC16(va_ + 16 * e_, vrow_ + 4 * e_);                                     \
    } } while (0)

__global__ void __launch_bounds__(256, 1) attn_tc_kernel() {
    extern __shared__ float sm[];
    const uint32_t sb = smem_u32(sm);
    float* sQ = sm;
    float* sP = sm + SP_OFF;

    const int p = blockIdx.x, h = blockIdx.y;
    const int tid = threadIdx.x;
    const int w = tid >> 5, lane = tid & 31;
    const int lq = lane >> 2, lr = lane & 3;

    // group 0: Q (raw) + KV block 0
    {
        const float* qrow = g_qkv + (size_t)(p * 256 + tid) * QKVD + h * 64;
        #pragma unroll
        for (int e = 0; e < 16; e++)
            CP_ASYNC16(sb + (uint32_t)((tid * AQ_STR + 4 * e) * 4), qrow + 4 * e);
        ATT_ISSUE(0, 0);
        CP_COMMIT;
    }

    float oacc[64];
    #pragma unroll
    for (int i = 0; i < 64; i++) oacc[i] = 0.f;
    float mrow[4] = {-1e30f, -1e30f, -1e30f, -1e30f};
    float lrow[4] = {0.f, 0.f, 0.f, 0.f};

    for (int kb = 0; kb < 4; kb++) {
        const int s = kb & 1;
        if (kb + 1 < 4) { ATT_ISSUE(kb + 1, (kb + 1) & 1); }
        CP_COMMIT;
        CP_WAIT1;
        __syncthreads();

        const float* sK = sm + SK_OFF + s * A_STG;
        const float* sV = sK + 64 * AK_STR;

        // S = Q_warp(32x64) @ K_blk^T(64x64)
        float sacc[64];
        #pragma unroll
        for (int i = 0; i < 64; i++) sacc[i] = 0.f;
        #pragma unroll
        for (int q = 0; q < 8; q++) {
            uint32_t af[2][4];
            #pragma unroll
            for (int am = 0; am < 2; am++) {
                int R = 32 * w + 16 * am + lq;
                int col = lr + 8 * q;
                af[am][0] = __float_as_uint(sQ[R * AQ_STR + col]);
                af[am][1] = __float_as_uint(sQ[(R + 8) * AQ_STR + col]);
                af[am][2] = __float_as_uint(sQ[R * AQ_STR + col + 4]);
                af[am][3] = __float_as_uint(sQ[(R + 8) * AQ_STR + col + 4]);
            }
            uint32_t bf[8][2];
            #pragma unroll
            for (int bn = 0; bn < 8; bn++) {
                int key = 8 * bn + lq;
                bf[bn][0] = __float_as_uint(sK[key * AK_STR + lr + 8 * q]);
                bf[bn][1] = __float_as_uint(sK[key * AK_STR + lr + 4 + 8 * q]);
            }
            #pragma unroll
            for (int am = 0; am < 2; am++)
                #pragma unroll
                for (int bn = 0; bn < 8; bn++)
                    mma_tf32(&sacc[(am * 8 + bn) * 4], af[am], bf[bn]);
        }

        // online softmax per row-slot (P stored raw)
        #pragma unroll
        for (int s4 = 0; s4 < 4; s4++) {
            int am = s4 >> 1, hi = s4 & 1;
            float vmax = -1e30f;
            #pragma unroll
            for (int bn = 0; bn < 8; bn++) {
                float v0 = sacc[(am * 8 + bn) * 4 + 2 * hi] * 0.125f;
                float v1 = sacc[(am * 8 + bn) * 4 + 2 * hi + 1] * 0.125f;
                vmax = fmaxf(vmax, fmaxf(v0, v1));
            }
            vmax = fmaxf(vmax, __shfl_xor_sync(0xffffffffu, vmax, 1));
            vmax = fmaxf(vmax, __shfl_xor_sync(0xffffffffu, vmax, 2));
            float newm = fmaxf(mrow[s4], vmax);
            float corr = __expf(mrow[s4] - newm);
            mrow[s4] = newm;
            float rsum = 0.f;
            int R = 32 * w + 16 * am + 8 * hi + lq;
            #pragma unroll
            for (int bn = 0; bn < 8; bn++) {
                float v0 = sacc[(am * 8 + bn) * 4 + 2 * hi] * 0.125f;
                float v1 = sacc[(am * 8 + bn) * 4 + 2 * hi + 1] * 0.125f;
                float p0 = __expf(v0 - newm), p1 = __expf(v1 - newm);
                rsum += p0 + p1;
                *(float2*)&sP[R * AP_STR + 8 * bn + 2 * lr] = make_float2(p0, p1);
            }
            rsum += __shfl_xor_sync(0xffffffffu, rsum, 1);
            rsum += __shfl_xor_sync(0xffffffffu, rsum, 2);
            lrow[s4] = lrow[s4] * corr + rsum;
            #pragma unroll
            for (int bn = 0; bn < 8; bn++) {
                oacc[(am * 8 + bn) * 4 + 2 * hi]     *= corr;
                oacc[(am * 8 + bn) * 4 + 2 * hi + 1] *= corr;
            }
        }
        __syncwarp();

        // O += P(32x64) @ V(64x64)
        #pragma unroll
        for (int q = 0; q < 8; q++) {
            uint32_t af[2][4];
            #pragma unroll
            for (int am = 0; am < 2; am++) {
                int R = 32 * w + 16 * am + lq;
                int col = lr + 8 * q;
                af[am][0] = __float_as_uint(sP[R * AP_STR + col]);
                af[am][1] = __float_as_uint(sP[(R + 8) * AP_STR + col]);
                af[am][2] = __float_as_uint(sP[R * AP_STR + col + 4]);
                af[am][3] = __float_as_uint(sP[(R + 8) * AP_STR + col + 4]);
            }
            uint32_t bf[8][2];
            #pragma unroll
            for (int bn = 0; bn < 8; bn++) {
                int d = 8 * bn + lq;
                bf[bn][0] = __float_as_uint(sV[(8 * q + lr) * AV_STR + d]);
                bf[bn][1] = __float_as_uint(sV[(8 * q + lr + 4) * AV_STR + d]);
            }
            #pragma unroll
            for (int am = 0; am < 2; am++)
                #pragma unroll
                for (int bn = 0; bn < 8; bn++)
                    mma_tf32(&oacc[(am * 8 + bn) * 4], af[am], bf[bn]);
        }
        __syncthreads();   // all reads of stage s done before it is overwritten
    }

    float inv[4];
    #pragma unroll
    for (int s4 = 0; s4 < 4; s4++) inv[s4] = 1.f / lrow[s4];
    #pragma unroll
    for (int am = 0; am < 2; am++) {
        int R0 = 32 * w + 16 * am + lq;
        #pragma unroll
        for (int bn = 0; bn < 8; bn++) {
            const int ix = (am * 8 + bn) * 4;
            *(float2*)&sP[R0 * AP_STR + 8 * bn + 2 * lr] =
                make_float2(oacc[ix + 0] * inv[2 * am], oacc[ix + 1] * inv[2 * am]);
            *(float2*)&sP[(R0 + 8) * AP_STR + 8 * bn + 2 * lr] =
                make_float2(oacc[ix + 2] * inv[2 * am + 1], oacc[ix + 3] * inv[2 * am + 1]);
        }
    }
    __syncthreads();
    {
        float* orow = g_att + (size_t)(p * 256 + tid) * CD + h * 64;
        #pragma unroll
        for (int k = 0; k < 16; k++)
            *(float4*)(orow + 4 * k) = *(const float4*)&sP[tid * AP_STR + 4 * k];
    }
}

// ================= scatter (coalesced) =================
__global__ void __launch_bounds__(384) scatter_kernel(float* __restrict__ out) {
    int run = blockIdx.x;
    int p = run >> 5, td = (run >> 3) & 3, th = run & 7;
    int bd = p >> 6, bh = (p >> 3) & 7, bw = p & 7;
    int od = (bd * 4 + td + 2) & 15;
    int oh = (bh * 8 + th + 4) & 63;
    int w0 = (bw * 8 + 4) & 63;
    int w1 = (bw * 8 + 8) & 63;
    int n0 = p * 256 + td * 64 + th * 8;

    int c = threadIdx.x;
    float v[8];
    #pragma unroll
    for (int j = 0; j < 8; j++) v[j] = g_y[(size_t)(n0 + j) * CD + c];
    float* base = out + (size_t)c * DHW + od * HW + oh * 64;
    *(float4*)(base + w0) = make_float4(v[0], v[1], v[2], v[3]);
    *(float4*)(base + w1) = make_float4(v[4], v[5], v[6], v[7]);
}

// ================= host launch =================
extern "C" void kernel_launch(void* const* d_in, const int* in_sizes, int n_in,
                              void* d_out, int out_size) {
    const float* x     = (const float*)d_in[0];
    const float* Wq    = (const float*)d_in[1];
    const float* bq    = (const float*)d_in[2];
    const float* Wk    = (const float*)d_in[3];
    const float* bk    = (const float*)d_in[4];
    const float* Wv    = (const float*)d_in[5];
    const float* bv    = (const float*)d_in[6];
    const float* Wo    = (const float*)d_in[7];
    const float* bo    = (const float*)d_in[8];
    const float* ln1_g = (const float*)d_in[9];
    const float* ln1_b = (const float*)d_in[10];
    const float* ln2_g = (const float*)d_in[11];
    const float* ln2_b = (const float*)d_in[12];
    const float* W1    = (const float*)d_in[13];
    const float* b1    = (const float*)d_in[14];
    const float* W2    = (const float*)d_in[15];
    const float* b2    = (const float*)d_in[16];
    float* out = (float*)d_out;

    float *p_h, *p_qkv, *p_att, *p_xw, *p_xw2, *p_h2, *p_hid, *p_y, *p_wqkv, *p_bqkv;
    cudaGetSymbolAddress((void**)&p_h,    g_h);
    cudaGetSymbolAddress((void**)&p_qkv,  g_qkv);
    cudaGetSymbolAddress((void**)&p_att,  g_att);
    cudaGetSymbolAddress((void**)&p_xw,   g_xw);
    cudaGetSymbolAddress((void**)&p_xw2,  g_xw2);
    cudaGetSymbolAddress((void**)&p_h2,   g_h2);
    cudaGetSymbolAddress((void**)&p_hid,  g_hid);
    cudaGetSymbolAddress((void**)&p_y,    g_y);
    cudaGetSymbolAddress((void**)&p_wqkv, g_wqkv);
    cudaGetSymbolAddress((void**)&p_bqkv, g_bqkv);

    cudaFuncSetAttribute(attn_tc_kernel, cudaFuncAttributeMaxDynamicSharedMemorySize, ATT_SMEM);
    cudaFuncSetAttribute(tgemm_kernel<0>, cudaFuncAttributeMaxDynamicSharedMemorySize, TG_SMEM);
    cudaFuncSetAttribute(tgemm_kernel<1>, cudaFuncAttributeMaxDynamicSharedMemorySize, TG_SMEM);
    cudaFuncSetAttribute(tgemm_kernel<2>, cudaFuncAttributeMaxDynamicSharedMemorySize, TG_SMEM);

    // 0) QKV weight/bias concat
    concat_qkv_kernel<<<384, 384>>>(Wq, Wk, Wv);
    bias_concat_kernel<<<3, 384>>>(bq, bk, bv);

    // 1) gather + LN1
    gather_ln1_kernel<<<8192, 384>>>(x, ln1_g, ln1_b);

    // 2) fused QKV projection  (grid: x = col tiles FAST, y = row tiles)
    tgemm_kernel<0><<<dim3(9, 512), 256, TG_SMEM>>>(p_h, p_wqkv, p_bqkv, nullptr, p_qkv, 384, QKVD);

    // 3) attention
    attn_tc_kernel<<<dim3(NWIN, NHEADS), 256, ATT_SMEM>>>();

    // 4) output projection + residual
    tgemm_kernel<1><<<dim3(3, 512), 256, TG_SMEM>>>(p_att, Wo, bo, p_xw, p_xw2, 384, 384);

    // 5) LN2
    ln2_kernel<<<NTOK, 384>>>(ln2_g, ln2_b);

    // 6) MLP
    tgemm_kernel<2><<<dim3(12, 512), 256, TG_SMEM>>>(p_h2, W1, b1, nullptr, p_hid, 384, MLPD);
    tgemm_kernel<1><<<dim3(3, 512), 256, TG_SMEM>>>(p_hid, W2, b2, p_xw2, p_y, MLPD, 384);

    // 7) scatter back
    scatter_kernel<<<8192, 384>>>(out);
}